// round 6
// baseline (speedup 1.0000x reference)
#include <cuda_runtime.h>

#define BATCH 1024
#define T     336
#define PRED  96
#define D     64
#define HD    64
#define G     256
#define NROWS (BATCH * T)

typedef unsigned long long ull;

// Scratch (device globals: allocation-free per harness rules)
__device__ float g_p[(size_t)BATCH * T * G];       // gate pre-acts (352 MB)
__device__ float g_h1[(size_t)BATCH * T * HD];     // layer-0 hidden states (88 MB)
__device__ float g_h2last[BATCH * HD];

// Packed fp32x2 FMA (Blackwell — PTX-only)
#define FMA2(acc, a, b) \
    asm("fma.rn.f32x2 %0, %1, %2, %0;" : "+l"(acc) : "l"(a), "l"(b))
#define UNPACK2(lo, hi, v) \
    asm("mov.b64 {%0, %1}, %2;" : "=f"(lo), "=f"(hi) : "l"(v))

// HW tanh unit: 1 MUFU
__device__ __forceinline__ float fast_tanh(float x) {
    float y;
    asm("tanh.approx.f32 %0, %1;" : "=f"(y) : "f"(x));
    return y;
}
__device__ __forceinline__ float fast_sigmoid(float x) {
    return fmaf(fast_tanh(0.5f * x), 0.5f, 0.5f);
}

// ---------------------------------------------------------------------------
// Input GEMM (persistent, 256 thr, 2 CTAs/SM): 16-row tiles.
// P[r][g] = In[r]·W[g] + b1[g] + b2[g]
// ---------------------------------------------------------------------------
__global__ void __launch_bounds__(256, 2) input_gemm(
    const float* __restrict__ In,   // [N, 64]
    const float* __restrict__ W,    // [256, 64]
    const float* __restrict__ b1,
    const float* __restrict__ b2,
    float* __restrict__ P,          // [N, 256]
    int N)
{
    __shared__ __align__(16) float sX[2][16 * 64];

    const int tid = threadIdx.x;
    const int g   = tid;

    ull w[32];
    {
        const ull* wp = (const ull*)(W + g * 64);
        #pragma unroll
        for (int i = 0; i < 32; i++) w[i] = wp[i];
    }
    const float bias = b1[g] + b2[g];

    const int ntiles = N / 16;          // 21504
    const int stride = gridDim.x;
    int tile = blockIdx.x;
    if (tile >= ntiles) return;

    float4 xr = *(const float4*)(In + (size_t)tile * (16 * 64) + tid * 4);
    *(float4*)&sX[0][tid * 4] = xr;
    __syncthreads();

    int buf = 0;
    for (; tile < ntiles; tile += stride) {
        const int nxt = tile + stride;
        if (nxt < ntiles)
            xr = *(const float4*)(In + (size_t)nxt * (16 * 64) + tid * 4);

        ull acc[16];
        #pragma unroll
        for (int r = 0; r < 16; r++) acc[r] = 0ull;

        const float* xb = sX[buf];
        #pragma unroll
        for (int kg = 0; kg < 16; kg++) {
            ull w01 = w[2 * kg], w23 = w[2 * kg + 1];
            #pragma unroll
            for (int r = 0; r < 16; r++) {
                ulonglong2 xv = *(const ulonglong2*)&xb[r * 64 + kg * 4];
                FMA2(acc[r], w01, xv.x);
                FMA2(acc[r], w23, xv.y);
            }
        }

        if (nxt < ntiles)
            *(float4*)&sX[buf ^ 1][tid * 4] = xr;

        float* prow = P + (size_t)tile * 16 * G + g;
        #pragma unroll
        for (int r = 0; r < 16; r++) {
            float lo, hi;
            UNPACK2(lo, hi, acc[r]);
            __stcs(&prow[(size_t)r * G], lo + hi + bias);
        }
        __syncthreads();
        buf ^= 1;
    }
}

// ---------------------------------------------------------------------------
// Recurrent scan v3: warp = (4 gate-types x 8 j), lane (gt,j8) owns gate row
// gt*64+j AND batch row b=gt. Cell update via warp shuffles — no sGate smem,
// ONE barrier per step (sH double-buffered to kill the WAR barrier).
// ---------------------------------------------------------------------------
template <bool WRITE_ALL>
__global__ void __launch_bounds__(256, 2) lstm_recur(
    const float* __restrict__ P,     // [BATCH, T, 256] (biases included)
    const float* __restrict__ Whh,   // [256, 64]
    float* __restrict__ hout)        // WRITE_ALL ? [BATCH,T,64] : [BATCH,64]
{
    __shared__ __align__(16) float sHb[2][4 * 64];

    const int tid  = threadIdx.x;
    const int lane = tid & 31;
    const int wrp  = tid >> 5;           // 0..7
    const int gt   = lane >> 3;          // 0..3 (gate type, also batch row owned)
    const int j8   = lane & 7;
    const int j    = wrp * 8 + j8;       // 0..63
    const int g    = gt * 64 + j;        // this thread's gate row
    const int b0   = blockIdx.x * 4;

    ull w[32];
    {
        const ull* wp = (const ull*)(Whh + g * 64);
        #pragma unroll
        for (int i = 0; i < 32; i++) w[i] = wp[i];
    }

    // branchless activation: act = fma(tanh(v*ta), s1, s2)
    const float ta = (gt == 2) ? 1.0f : 0.5f;
    const float s1 = (gt == 2) ? 1.0f : 0.5f;
    const float s2 = (gt == 2) ? 0.0f : 0.5f;

    float c = 0.0f;
    sHb[0][tid] = 0.0f;

    // P pointers: row (b0+b)*T + t, column g
    const float* pbase = P + ((size_t)b0 * T) * G + g;
    float pc[4];
    #pragma unroll
    for (int b = 0; b < 4; b++) pc[b] = pbase[(size_t)b * T * G];
    __syncthreads();

    int p = 0;
    for (int t = 0; t < T; t++) {
        float pn[4];
        if (t + 1 < T) {
            #pragma unroll
            for (int b = 0; b < 4; b++)
                pn[b] = __ldcs(&pbase[(size_t)b * T * G + (size_t)(t + 1) * G]);
        }

        ull acc[4];
        #pragma unroll
        for (int b = 0; b < 4; b++) acc[b] = 0ull;

        const float* sH = sHb[p];
        #pragma unroll
        for (int kg = 0; kg < 16; kg++) {
            ull w01 = w[2 * kg], w23 = w[2 * kg + 1];
            #pragma unroll
            for (int b = 0; b < 4; b++) {
                ulonglong2 hv = *(const ulonglong2*)&sH[b * 64 + kg * 4];
                FMA2(acc[b], w01, hv.x);
                FMA2(acc[b], w23, hv.y);
            }
        }

        // activate (branchless, per-lane constants)
        float act[4];
        #pragma unroll
        for (int b = 0; b < 4; b++) {
            float lo, hi;
            UNPACK2(lo, hi, acc[b]);
            float v = lo + hi + pc[b];
            act[b] = fmaf(fast_tanh(v * ta), s1, s2);
        }

        // warp-local gate exchange + cell update (lane owns (b=gt, j))
        float hmine = 0.0f;
        #pragma unroll
        for (int b = 0; b < 4; b++) {
            float ai = __shfl_sync(0xffffffffu, act[b], j8);
            float af = __shfl_sync(0xffffffffu, act[b], 8 + j8);
            float ag = __shfl_sync(0xffffffffu, act[b], 16 + j8);
            float ao = __shfl_sync(0xffffffffu, act[b], 24 + j8);
            if (gt == b) {
                c = fmaf(af, c, ai * ag);
                hmine = ao * fast_tanh(c);
            }
        }

        // write new h to the other buffer; single barrier
        sHb[p ^ 1][gt * 64 + j] = hmine;
        if (WRITE_ALL) {
            __stcs(&hout[(size_t)(b0 + gt) * T * HD + (size_t)t * HD + j], hmine);
        } else if (t == T - 1) {
            hout[(b0 + gt) * HD + j] = hmine;
        }
        __syncthreads();
        p ^= 1;

        #pragma unroll
        for (int b = 0; b < 4; b++) pc[b] = pn[b];
    }
}

// ---------------------------------------------------------------------------
// Decoder: 512 threads, BT=8. Half-split register weights.
// ---------------------------------------------------------------------------
__global__ void __launch_bounds__(512, 1) lstm_decoder(
    const float* __restrict__ Wih0, const float* __restrict__ bih0, const float* __restrict__ bhh0,
    const float* __restrict__ Wih1, const float* __restrict__ bih1, const float* __restrict__ bhh1,
    const float* __restrict__ Wfc,  const float* __restrict__ bfc,
    const float* __restrict__ h2last,
    float* __restrict__ out)   // [BATCH, PRED, 64]
{
    __shared__ __align__(16) ull   sWfcp[32 * 64];   // [kpair][j] packed (16 KB)
    __shared__ float sBfc[64];
    __shared__ __align__(16) float sIn[8 * 64];
    __shared__ __align__(16) float sHm[8 * 64];
    __shared__ __align__(16) float sGate[8 * G];

    const int tid  = threadIdx.x;
    const int b0   = blockIdx.x * 8;
    const int half = tid >> 8;           // 0: cell0 gates, 1: cell1 gates
    const int hg   = tid & 255;
    const int gt   = hg >> 6;
    const int eb   = tid >> 6;           // 0..7
    const int ej   = tid & 63;

    ull w[32];
    {
        const float* wsrc = half ? (Wih1 + hg * 64) : (Wih0 + hg * 64);
        const ull* wp = (const ull*)wsrc;
        #pragma unroll
        for (int i = 0; i < 32; i++) w[i] = wp[i];
    }
    const float bias = half ? (bih1[hg] + bhh1[hg]) : (bih0[hg] + bhh0[hg]);
    const float ta = (gt == 2) ? 1.0f : 0.5f;
    const float s1 = (gt == 2) ? 1.0f : 0.5f;
    const float s2 = (gt == 2) ? 0.0f : 0.5f;

    if (tid < 64) {
        const ull* wf = (const ull*)(Wfc + tid * 64);
        #pragma unroll
        for (int i = 0; i < 32; i++) sWfcp[i * 64 + tid] = wf[i];
        sBfc[tid] = bfc[tid];
    }
    sIn[tid] = h2last[b0 * 64 + tid];
    __syncthreads();

    for (int s = 0; s < PRED; s++) {
        // ---- cell0: lower half computes gates from sIn ----
        if (half == 0) {
            ull acc[8];
            #pragma unroll
            for (int b = 0; b < 8; b++) acc[b] = 0ull;
            #pragma unroll
            for (int kg = 0; kg < 16; kg++) {
                ull w01 = w[2 * kg], w23 = w[2 * kg + 1];
                #pragma unroll
                for (int b = 0; b < 8; b++) {
                    ulonglong2 xv = *(const ulonglong2*)&sIn[b * 64 + kg * 4];
                    FMA2(acc[b], w01, xv.x);
                    FMA2(acc[b], w23, xv.y);
                }
            }
            #pragma unroll
            for (int b = 0; b < 8; b++) {
                float lo, hi;
                UNPACK2(lo, hi, acc[b]);
                float v = lo + hi + bias;
                sGate[b * G + hg] = fmaf(fast_tanh(v * ta), s1, s2);
            }
        }
        __syncthreads();
        {
            float iv = sGate[eb * G + ej];
            float gv = sGate[eb * G + 128 + ej];
            float ov = sGate[eb * G + 192 + ej];
            sHm[tid] = ov * fast_tanh(iv * gv);
        }
        __syncthreads();

        // ---- cell1: upper half computes gates from sHm ----
        if (half == 1) {
            ull acc[8];
            #pragma unroll
            for (int b = 0; b < 8; b++) acc[b] = 0ull;
            #pragma unroll
            for (int kg = 0; kg < 16; kg++) {
                ull w01 = w[2 * kg], w23 = w[2 * kg + 1];
                #pragma unroll
                for (int b = 0; b < 8; b++) {
                    ulonglong2 xv = *(const ulonglong2*)&sHm[b * 64 + kg * 4];
                    FMA2(acc[b], w01, xv.x);
                    FMA2(acc[b], w23, xv.y);
                }
            }
            #pragma unroll
            for (int b = 0; b < 8; b++) {
                float lo, hi;
                UNPACK2(lo, hi, acc[b]);
                float v = lo + hi + bias;
                sGate[b * G + hg] = fmaf(fast_tanh(v * ta), s1, s2);
            }
        }
        __syncthreads();
        {
            float iv = sGate[eb * G + ej];
            float gv = sGate[eb * G + 128 + ej];
            float ov = sGate[eb * G + 192 + ej];
            sHm[tid] = ov * fast_tanh(iv * gv);
        }
        __syncthreads();

        // ---- FC: one output per thread (eb, ej) ----
        {
            ull acc = 0ull;
            #pragma unroll
            for (int i = 0; i < 16; i++) {
                ull w01 = sWfcp[(2 * i) * 64 + ej];
                ull w23 = sWfcp[(2 * i + 1) * 64 + ej];
                ulonglong2 xv = *(const ulonglong2*)&sHm[eb * 64 + i * 4];
                FMA2(acc, w01, xv.x);
                FMA2(acc, w23, xv.y);
            }
            float lo, hi;
            UNPACK2(lo, hi, acc);
            float pred = lo + hi + sBfc[ej];
            out[(size_t)(b0 + eb) * PRED * HD + (size_t)s * HD + ej] = pred;
            sIn[tid] = pred;
            __syncthreads();
        }
    }
}

// ---------------------------------------------------------------------------
extern "C" void kernel_launch(void* const* d_in, const int* in_sizes, int n_in,
                              void* d_out, int out_size)
{
    const float* x    = (const float*)d_in[0];
    const float* Wih0 = (const float*)d_in[1];
    const float* Whh0 = (const float*)d_in[2];
    const float* bih0 = (const float*)d_in[3];
    const float* bhh0 = (const float*)d_in[4];
    const float* Wih1 = (const float*)d_in[5];
    const float* Whh1 = (const float*)d_in[6];
    const float* bih1 = (const float*)d_in[7];
    const float* bhh1 = (const float*)d_in[8];
    const float* Wfc  = (const float*)d_in[9];
    const float* bfc  = (const float*)d_in[10];
    float* out = (float*)d_out;

    float *pbuf = nullptr, *h1 = nullptr, *h2l = nullptr;
    cudaGetSymbolAddress((void**)&pbuf, g_p);
    cudaGetSymbolAddress((void**)&h1,   g_h1);
    cudaGetSymbolAddress((void**)&h2l,  g_h2last);

    input_gemm<<<296, 256>>>(x, Wih0, bih0, bhh0, pbuf, NROWS);
    lstm_recur<true ><<<256, 256>>>(pbuf, Whh0, h1);

    input_gemm<<<296, 256>>>(h1, Wih1, bih1, bhh1, pbuf, NROWS);
    lstm_recur<false><<<256, 256>>>(pbuf, Whh1, h2l);

    lstm_decoder<<<128, 512>>>(Wih0, bih0, bhh0, Wih1, bih1, bhh1,
                               Wfc, bfc, h2l, out);
}

// round 7
// speedup vs baseline: 1.0020x; 1.0020x over previous
#include <cuda_runtime.h>

#define BATCH 1024
#define T     336
#define PRED  96
#define D     64
#define HD    64
#define G     256
#define NROWS (BATCH * T)

typedef unsigned long long ull;

// Scratch (device globals: allocation-free per harness rules)
__device__ float g_p[(size_t)BATCH * T * G];       // gate pre-acts (352 MB)
__device__ float g_h1[(size_t)BATCH * T * HD];     // layer-0 hidden states (88 MB)
__device__ float g_h2last[BATCH * HD];

// Packed fp32x2 FMA (Blackwell — PTX-only)
#define FMA2(acc, a, b) \
    asm("fma.rn.f32x2 %0, %1, %2, %0;" : "+l"(acc) : "l"(a), "l"(b))
#define UNPACK2(lo, hi, v) \
    asm("mov.b64 {%0, %1}, %2;" : "=f"(lo), "=f"(hi) : "l"(v))

// HW tanh unit: 1 MUFU
__device__ __forceinline__ float fast_tanh(float x) {
    float y;
    asm("tanh.approx.f32 %0, %1;" : "=f"(y) : "f"(x));
    return y;
}
__device__ __forceinline__ float fast_sigmoid(float x) {
    return fmaf(fast_tanh(0.5f * x), 0.5f, 0.5f);
}

// ---------------------------------------------------------------------------
// Input GEMM (persistent, 256 thr, 2 CTAs/SM): 16-row tiles.
// P[r][g] = In[r]·W[g] + b1[g] + b2[g]
// ---------------------------------------------------------------------------
__global__ void __launch_bounds__(256, 2) input_gemm(
    const float* __restrict__ In,   // [N, 64]
    const float* __restrict__ W,    // [256, 64]
    const float* __restrict__ b1,
    const float* __restrict__ b2,
    float* __restrict__ P,          // [N, 256]
    int N)
{
    __shared__ __align__(16) float sX[2][16 * 64];

    const int tid = threadIdx.x;
    const int g   = tid;

    ull w[32];
    {
        const ull* wp = (const ull*)(W + g * 64);
        #pragma unroll
        for (int i = 0; i < 32; i++) w[i] = wp[i];
    }
    const float bias = b1[g] + b2[g];

    const int ntiles = N / 16;          // 21504
    const int stride = gridDim.x;
    int tile = blockIdx.x;
    if (tile >= ntiles) return;

    float4 xr = *(const float4*)(In + (size_t)tile * (16 * 64) + tid * 4);
    *(float4*)&sX[0][tid * 4] = xr;
    __syncthreads();

    int buf = 0;
    for (; tile < ntiles; tile += stride) {
        const int nxt = tile + stride;
        if (nxt < ntiles)
            xr = *(const float4*)(In + (size_t)nxt * (16 * 64) + tid * 4);

        ull acc[16];
        #pragma unroll
        for (int r = 0; r < 16; r++) acc[r] = 0ull;

        const float* xb = sX[buf];
        #pragma unroll
        for (int kg = 0; kg < 16; kg++) {
            ull w01 = w[2 * kg], w23 = w[2 * kg + 1];
            #pragma unroll
            for (int r = 0; r < 16; r++) {
                ulonglong2 xv = *(const ulonglong2*)&xb[r * 64 + kg * 4];
                FMA2(acc[r], w01, xv.x);
                FMA2(acc[r], w23, xv.y);
            }
        }

        if (nxt < ntiles)
            *(float4*)&sX[buf ^ 1][tid * 4] = xr;

        float* prow = P + (size_t)tile * 16 * G + g;
        #pragma unroll
        for (int r = 0; r < 16; r++) {
            float lo, hi;
            UNPACK2(lo, hi, acc[r]);
            __stcs(&prow[(size_t)r * G], lo + hi + bias);
        }
        __syncthreads();
        buf ^= 1;
    }
}

// ---------------------------------------------------------------------------
// Recurrent scan v3: warp = (4 gate-types x 8 j), lane (gt,j8) owns gate row
// gt*64+j AND batch row b=gt. Cell update via warp shuffles — no sGate smem,
// ONE barrier per step (sH double-buffered to kill the WAR barrier).
// ---------------------------------------------------------------------------
template <bool WRITE_ALL>
__global__ void __launch_bounds__(256, 2) lstm_recur(
    const float* __restrict__ P,     // [BATCH, T, 256] (biases included)
    const float* __restrict__ Whh,   // [256, 64]
    float* __restrict__ hout)        // WRITE_ALL ? [BATCH,T,64] : [BATCH,64]
{
    __shared__ __align__(16) float sHb[2][4 * 64];

    const int tid  = threadIdx.x;
    const int lane = tid & 31;
    const int wrp  = tid >> 5;           // 0..7
    const int gt   = lane >> 3;          // 0..3 (gate type, also batch row owned)
    const int j8   = lane & 7;
    const int j    = wrp * 8 + j8;       // 0..63
    const int g    = gt * 64 + j;        // this thread's gate row
    const int b0   = blockIdx.x * 4;

    ull w[32];
    {
        const ull* wp = (const ull*)(Whh + g * 64);
        #pragma unroll
        for (int i = 0; i < 32; i++) w[i] = wp[i];
    }

    // branchless activation: act = fma(tanh(v*ta), s1, s2)
    const float ta = (gt == 2) ? 1.0f : 0.5f;
    const float s1 = (gt == 2) ? 1.0f : 0.5f;
    const float s2 = (gt == 2) ? 0.0f : 0.5f;

    float c = 0.0f;
    sHb[0][tid] = 0.0f;

    // P pointers: row (b0+b)*T + t, column g
    const float* pbase = P + ((size_t)b0 * T) * G + g;
    float pc[4];
    #pragma unroll
    for (int b = 0; b < 4; b++) pc[b] = pbase[(size_t)b * T * G];
    __syncthreads();

    int p = 0;
    for (int t = 0; t < T; t++) {
        float pn[4];
        if (t + 1 < T) {
            #pragma unroll
            for (int b = 0; b < 4; b++)
                pn[b] = __ldcs(&pbase[(size_t)b * T * G + (size_t)(t + 1) * G]);
        }

        ull acc[4];
        #pragma unroll
        for (int b = 0; b < 4; b++) acc[b] = 0ull;

        const float* sH = sHb[p];
        #pragma unroll
        for (int kg = 0; kg < 16; kg++) {
            ull w01 = w[2 * kg], w23 = w[2 * kg + 1];
            #pragma unroll
            for (int b = 0; b < 4; b++) {
                ulonglong2 hv = *(const ulonglong2*)&sH[b * 64 + kg * 4];
                FMA2(acc[b], w01, hv.x);
                FMA2(acc[b], w23, hv.y);
            }
        }

        // activate (branchless, per-lane constants)
        float act[4];
        #pragma unroll
        for (int b = 0; b < 4; b++) {
            float lo, hi;
            UNPACK2(lo, hi, acc[b]);
            float v = lo + hi + pc[b];
            act[b] = fmaf(fast_tanh(v * ta), s1, s2);
        }

        // warp-local gate exchange + cell update (lane owns (b=gt, j))
        float hmine = 0.0f;
        #pragma unroll
        for (int b = 0; b < 4; b++) {
            float ai = __shfl_sync(0xffffffffu, act[b], j8);
            float af = __shfl_sync(0xffffffffu, act[b], 8 + j8);
            float ag = __shfl_sync(0xffffffffu, act[b], 16 + j8);
            float ao = __shfl_sync(0xffffffffu, act[b], 24 + j8);
            if (gt == b) {
                c = fmaf(af, c, ai * ag);
                hmine = ao * fast_tanh(c);
            }
        }

        // write new h to the other buffer; single barrier
        sHb[p ^ 1][gt * 64 + j] = hmine;
        if (WRITE_ALL) {
            __stcs(&hout[(size_t)(b0 + gt) * T * HD + (size_t)t * HD + j], hmine);
        } else if (t == T - 1) {
            hout[(b0 + gt) * HD + j] = hmine;
        }
        __syncthreads();
        p ^= 1;

        #pragma unroll
        for (int b = 0; b < 4; b++) pc[b] = pn[b];
    }
}

// ---------------------------------------------------------------------------
// Decoder: 512 threads, BT=8. Half-split register weights.
// ---------------------------------------------------------------------------
__global__ void __launch_bounds__(512, 1) lstm_decoder(
    const float* __restrict__ Wih0, const float* __restrict__ bih0, const float* __restrict__ bhh0,
    const float* __restrict__ Wih1, const float* __restrict__ bih1, const float* __restrict__ bhh1,
    const float* __restrict__ Wfc,  const float* __restrict__ bfc,
    const float* __restrict__ h2last,
    float* __restrict__ out)   // [BATCH, PRED, 64]
{
    __shared__ __align__(16) ull   sWfcp[32 * 64];   // [kpair][j] packed (16 KB)
    __shared__ float sBfc[64];
    __shared__ __align__(16) float sIn[8 * 64];
    __shared__ __align__(16) float sHm[8 * 64];
    __shared__ __align__(16) float sGate[8 * G];

    const int tid  = threadIdx.x;
    const int b0   = blockIdx.x * 8;
    const int half = tid >> 8;           // 0: cell0 gates, 1: cell1 gates
    const int hg   = tid & 255;
    const int gt   = hg >> 6;
    const int eb   = tid >> 6;           // 0..7
    const int ej   = tid & 63;

    ull w[32];
    {
        const float* wsrc = half ? (Wih1 + hg * 64) : (Wih0 + hg * 64);
        const ull* wp = (const ull*)wsrc;
        #pragma unroll
        for (int i = 0; i < 32; i++) w[i] = wp[i];
    }
    const float bias = half ? (bih1[hg] + bhh1[hg]) : (bih0[hg] + bhh0[hg]);
    const float ta = (gt == 2) ? 1.0f : 0.5f;
    const float s1 = (gt == 2) ? 1.0f : 0.5f;
    const float s2 = (gt == 2) ? 0.0f : 0.5f;

    if (tid < 64) {
        const ull* wf = (const ull*)(Wfc + tid * 64);
        #pragma unroll
        for (int i = 0; i < 32; i++) sWfcp[i * 64 + tid] = wf[i];
        sBfc[tid] = bfc[tid];
    }
    sIn[tid] = h2last[b0 * 64 + tid];
    __syncthreads();

    for (int s = 0; s < PRED; s++) {
        // ---- cell0: lower half computes gates from sIn ----
        if (half == 0) {
            ull acc[8];
            #pragma unroll
            for (int b = 0; b < 8; b++) acc[b] = 0ull;
            #pragma unroll
            for (int kg = 0; kg < 16; kg++) {
                ull w01 = w[2 * kg], w23 = w[2 * kg + 1];
                #pragma unroll
                for (int b = 0; b < 8; b++) {
                    ulonglong2 xv = *(const ulonglong2*)&sIn[b * 64 + kg * 4];
                    FMA2(acc[b], w01, xv.x);
                    FMA2(acc[b], w23, xv.y);
                }
            }
            #pragma unroll
            for (int b = 0; b < 8; b++) {
                float lo, hi;
                UNPACK2(lo, hi, acc[b]);
                float v = lo + hi + bias;
                sGate[b * G + hg] = fmaf(fast_tanh(v * ta), s1, s2);
            }
        }
        __syncthreads();
        {
            float iv = sGate[eb * G + ej];
            float gv = sGate[eb * G + 128 + ej];
            float ov = sGate[eb * G + 192 + ej];
            sHm[tid] = ov * fast_tanh(iv * gv);
        }
        __syncthreads();

        // ---- cell1: upper half computes gates from sHm ----
        if (half == 1) {
            ull acc[8];
            #pragma unroll
            for (int b = 0; b < 8; b++) acc[b] = 0ull;
            #pragma unroll
            for (int kg = 0; kg < 16; kg++) {
                ull w01 = w[2 * kg], w23 = w[2 * kg + 1];
                #pragma unroll
                for (int b = 0; b < 8; b++) {
                    ulonglong2 xv = *(const ulonglong2*)&sHm[b * 64 + kg * 4];
                    FMA2(acc[b], w01, xv.x);
                    FMA2(acc[b], w23, xv.y);
                }
            }
            #pragma unroll
            for (int b = 0; b < 8; b++) {
                float lo, hi;
                UNPACK2(lo, hi, acc[b]);
                float v = lo + hi + bias;
                sGate[b * G + hg] = fmaf(fast_tanh(v * ta), s1, s2);
            }
        }
        __syncthreads();
        {
            float iv = sGate[eb * G + ej];
            float gv = sGate[eb * G + 128 + ej];
            float ov = sGate[eb * G + 192 + ej];
            sHm[tid] = ov * fast_tanh(iv * gv);
        }
        __syncthreads();

        // ---- FC: one output per thread (eb, ej) ----
        {
            ull acc = 0ull;
            #pragma unroll
            for (int i = 0; i < 16; i++) {
                ull w01 = sWfcp[(2 * i) * 64 + ej];
                ull w23 = sWfcp[(2 * i + 1) * 64 + ej];
                ulonglong2 xv = *(const ulonglong2*)&sHm[eb * 64 + i * 4];
                FMA2(acc, w01, xv.x);
                FMA2(acc, w23, xv.y);
            }
            float lo, hi;
            UNPACK2(lo, hi, acc);
            float pred = lo + hi + sBfc[ej];
            out[(size_t)(b0 + eb) * PRED * HD + (size_t)s * HD + ej] = pred;
            sIn[tid] = pred;
            __syncthreads();
        }
    }
}

// ---------------------------------------------------------------------------
extern "C" void kernel_launch(void* const* d_in, const int* in_sizes, int n_in,
                              void* d_out, int out_size)
{
    const float* x    = (const float*)d_in[0];
    const float* Wih0 = (const float*)d_in[1];
    const float* Whh0 = (const float*)d_in[2];
    const float* bih0 = (const float*)d_in[3];
    const float* bhh0 = (const float*)d_in[4];
    const float* Wih1 = (const float*)d_in[5];
    const float* Whh1 = (const float*)d_in[6];
    const float* bih1 = (const float*)d_in[7];
    const float* bhh1 = (const float*)d_in[8];
    const float* Wfc  = (const float*)d_in[9];
    const float* bfc  = (const float*)d_in[10];
    float* out = (float*)d_out;

    float *pbuf = nullptr, *h1 = nullptr, *h2l = nullptr;
    cudaGetSymbolAddress((void**)&pbuf, g_p);
    cudaGetSymbolAddress((void**)&h1,   g_h1);
    cudaGetSymbolAddress((void**)&h2l,  g_h2last);

    input_gemm<<<296, 256>>>(x, Wih0, bih0, bhh0, pbuf, NROWS);
    lstm_recur<true ><<<256, 256>>>(pbuf, Whh0, h1);

    input_gemm<<<296, 256>>>(h1, Wih1, bih1, bhh1, pbuf, NROWS);
    lstm_recur<false><<<256, 256>>>(pbuf, Whh1, h2l);

    lstm_decoder<<<128, 512>>>(Wih0, bih0, bhh0, Wih1, bih1, bhh1,
                               Wfc, bfc, h2l, out);
}

// round 8
// speedup vs baseline: 1.1081x; 1.1059x over previous
#include <cuda_runtime.h>

#define BATCH 1024
#define T     336
#define PRED  96
#define D     64
#define HD    64
#define G     256
#define NROWS (BATCH * T)

typedef unsigned long long ull;

// Scratch (device globals: allocation-free per harness rules)
__device__ float g_p[(size_t)BATCH * T * G];       // gate pre-acts (352 MB)
__device__ float g_h1[(size_t)BATCH * T * HD];     // layer-0 hidden states (88 MB)
__device__ float g_h2last[BATCH * HD];

// Packed fp32x2 FMA (Blackwell — PTX-only)
#define FMA2(acc, a, b) \
    asm("fma.rn.f32x2 %0, %1, %2, %0;" : "+l"(acc) : "l"(a), "l"(b))
#define UNPACK2(lo, hi, v) \
    asm("mov.b64 {%0, %1}, %2;" : "=f"(lo), "=f"(hi) : "l"(v))

// HW tanh unit: 1 MUFU
__device__ __forceinline__ float fast_tanh(float x) {
    float y;
    asm("tanh.approx.f32 %0, %1;" : "=f"(y) : "f"(x));
    return y;
}
__device__ __forceinline__ float fast_sigmoid(float x) {
    return fmaf(fast_tanh(0.5f * x), 0.5f, 0.5f);
}

// ---------------------------------------------------------------------------
// Input GEMM (persistent, 256 thr, 2 CTAs/SM): 16-row tiles.
// ---------------------------------------------------------------------------
__global__ void __launch_bounds__(256, 2) input_gemm(
    const float* __restrict__ In,   // [N, 64]
    const float* __restrict__ W,    // [256, 64]
    const float* __restrict__ b1,
    const float* __restrict__ b2,
    float* __restrict__ P,          // [N, 256]
    int N)
{
    __shared__ __align__(16) float sX[2][16 * 64];

    const int tid = threadIdx.x;
    const int g   = tid;

    ull w[32];
    {
        const ull* wp = (const ull*)(W + g * 64);
        #pragma unroll
        for (int i = 0; i < 32; i++) w[i] = wp[i];
    }
    const float bias = b1[g] + b2[g];

    const int ntiles = N / 16;
    const int stride = gridDim.x;
    int tile = blockIdx.x;
    if (tile >= ntiles) return;

    float4 xr = *(const float4*)(In + (size_t)tile * (16 * 64) + tid * 4);
    *(float4*)&sX[0][tid * 4] = xr;
    __syncthreads();

    int buf = 0;
    for (; tile < ntiles; tile += stride) {
        const int nxt = tile + stride;
        if (nxt < ntiles)
            xr = *(const float4*)(In + (size_t)nxt * (16 * 64) + tid * 4);

        ull acc[16];
        #pragma unroll
        for (int r = 0; r < 16; r++) acc[r] = 0ull;

        const float* xb = sX[buf];
        #pragma unroll
        for (int kg = 0; kg < 16; kg++) {
            ull w01 = w[2 * kg], w23 = w[2 * kg + 1];
            #pragma unroll
            for (int r = 0; r < 16; r++) {
                ulonglong2 xv = *(const ulonglong2*)&xb[r * 64 + kg * 4];
                FMA2(acc[r], w01, xv.x);
                FMA2(acc[r], w23, xv.y);
            }
        }

        if (nxt < ntiles)
            *(float4*)&sX[buf ^ 1][tid * 4] = xr;

        float* prow = P + (size_t)tile * 16 * G + g;
        #pragma unroll
        for (int r = 0; r < 16; r++) {
            float lo, hi;
            UNPACK2(lo, hi, acc[r]);
            __stcs(&prow[(size_t)r * G], lo + hi + bias);
        }
        __syncthreads();
        buf ^= 1;
    }
}

// ---------------------------------------------------------------------------
// Recurrent scan (R5 version — known good): BT=4, 256 thr, 2 CTAs/SM,
// smem gate exchange, 2 barriers/step, c in register.
// ---------------------------------------------------------------------------
template <bool WRITE_ALL>
__global__ void __launch_bounds__(256, 2) lstm_recur(
    const float* __restrict__ P,     // [BATCH, T, 256] (biases included)
    const float* __restrict__ Whh,   // [256, 64]
    float* __restrict__ hout)        // WRITE_ALL ? [BATCH,T,64] : [BATCH,64]
{
    __shared__ __align__(16) float sH[4 * 64];
    __shared__ __align__(16) float sGate[4 * G];

    const int tid = threadIdx.x;
    const int b0  = blockIdx.x * 4;
    const int g   = tid;
    const int gt  = g >> 6;              // warp-uniform

    ull w[32];
    {
        const ull* wp = (const ull*)(Whh + g * 64);
        #pragma unroll
        for (int i = 0; i < 32; i++) w[i] = wp[i];
    }

    const int eb = tid >> 6;             // 0..3
    const int ej = tid & 63;
    float c = 0.0f;

    sH[tid] = 0.0f;

    const float* pbase = P + ((size_t)b0 * T) * G + g;
    float pc[4];
    #pragma unroll
    for (int b = 0; b < 4; b++) pc[b] = pbase[(size_t)b * T * G];
    __syncthreads();

    for (int t = 0; t < T; t++) {
        float pn[4];
        if (t + 1 < T) {
            #pragma unroll
            for (int b = 0; b < 4; b++)
                pn[b] = __ldcs(&pbase[(size_t)b * T * G + (size_t)(t + 1) * G]);
        }

        ull acc[4];
        #pragma unroll
        for (int b = 0; b < 4; b++) acc[b] = 0ull;

        #pragma unroll
        for (int kg = 0; kg < 16; kg++) {
            ull w01 = w[2 * kg], w23 = w[2 * kg + 1];
            #pragma unroll
            for (int b = 0; b < 4; b++) {
                ulonglong2 hv = *(const ulonglong2*)&sH[b * 64 + kg * 4];
                FMA2(acc[b], w01, hv.x);
                FMA2(acc[b], w23, hv.y);
            }
        }

        #pragma unroll
        for (int b = 0; b < 4; b++) {
            float lo, hi;
            UNPACK2(lo, hi, acc[b]);
            float v = lo + hi + pc[b];
            sGate[b * G + g] = (gt == 2) ? fast_tanh(v) : fast_sigmoid(v);
        }
        __syncthreads();

        {
            float iv = sGate[eb * G + ej];
            float fv = sGate[eb * G + 64 + ej];
            float gv = sGate[eb * G + 128 + ej];
            float ov = sGate[eb * G + 192 + ej];
            c = fmaf(fv, c, iv * gv);
            float h = ov * fast_tanh(c);
            sH[tid] = h;
            if (WRITE_ALL) {
                __stcs(&hout[(size_t)(b0 + eb) * T * HD + (size_t)t * HD + ej], h);
            } else if (t == T - 1) {
                hout[(b0 + eb) * HD + ej] = h;
            }
        }
        __syncthreads();

        #pragma unroll
        for (int b = 0; b < 4; b++) pc[b] = pn[b];
    }
}

// ---------------------------------------------------------------------------
// Decoder v2: BT=4, 256 threads, grid 256 → 2 CTAs/SM. Every thread computes
// gate g in BOTH cells: cell0 weights in regs, cell1 weights from packed smem.
// FC: one output per thread. 5 barriers/step, hidden by co-resident CTA.
// ---------------------------------------------------------------------------
__global__ void __launch_bounds__(256, 2) lstm_decoder(
    const float* __restrict__ Wih0, const float* __restrict__ bih0, const float* __restrict__ bhh0,
    const float* __restrict__ Wih1, const float* __restrict__ bih1, const float* __restrict__ bhh1,
    const float* __restrict__ Wfc,  const float* __restrict__ bfc,
    const float* __restrict__ h2last,
    float* __restrict__ out)   // [BATCH, PRED, 64]
{
    extern __shared__ __align__(16) char dyn[];
    ull*   sW1p  = (ull*)dyn;                      // [32][256] ull (64 KB)
    ull*   sWfcp = sW1p + 32 * 256;                // [32][64]  ull (16 KB)
    float* sB1   = (float*)(sWfcp + 32 * 64);      // [256]
    float* sBfc  = sB1 + 256;                      // [64]
    float* sIn   = sBfc + 64;                      // [4][64]
    float* sHm   = sIn + 4 * 64;                   // [4][64]
    float* sGate = sHm + 4 * 64;                   // [4][256]

    const int tid = threadIdx.x;
    const int b0  = blockIdx.x * 4;
    const int g   = tid;
    const int gt  = g >> 6;
    const int eb  = tid >> 6;            // 0..3
    const int ej  = tid & 63;

    ull wa[32];
    {
        const ull* w0 = (const ull*)(Wih0 + g * 64);
        #pragma unroll
        for (int i = 0; i < 32; i++) wa[i] = w0[i];
    }
    const float bias0 = bih0[g] + bhh0[g];
    const float ta = (gt == 2) ? 1.0f : 0.5f;
    const float s1 = (gt == 2) ? 1.0f : 0.5f;
    const float s2 = (gt == 2) ? 0.0f : 0.5f;

    // fill smem weight tables (transposed pair layout)
    {
        const ull* w1 = (const ull*)(Wih1 + tid * 64);
        #pragma unroll
        for (int i = 0; i < 32; i++) sW1p[i * 256 + tid] = w1[i];
        sB1[tid] = bih1[tid] + bhh1[tid];
        if (tid < 64) {
            const ull* wf = (const ull*)(Wfc + tid * 64);
            #pragma unroll
            for (int i = 0; i < 32; i++) sWfcp[i * 64 + tid] = wf[i];
            sBfc[tid] = bfc[tid];
        }
    }
    sIn[tid] = h2last[b0 * 64 + tid];
    __syncthreads();

    for (int s = 0; s < PRED; s++) {
        // ---- cell0 (weights in regs), src = sIn ----
        {
            ull acc[4];
            #pragma unroll
            for (int b = 0; b < 4; b++) acc[b] = 0ull;
            #pragma unroll
            for (int kg = 0; kg < 16; kg++) {
                ull w01 = wa[2 * kg], w23 = wa[2 * kg + 1];
                #pragma unroll
                for (int b = 0; b < 4; b++) {
                    ulonglong2 xv = *(const ulonglong2*)&sIn[b * 64 + kg * 4];
                    FMA2(acc[b], w01, xv.x);
                    FMA2(acc[b], w23, xv.y);
                }
            }
            #pragma unroll
            for (int b = 0; b < 4; b++) {
                float lo, hi;
                UNPACK2(lo, hi, acc[b]);
                float v = lo + hi + bias0;
                sGate[b * G + g] = fmaf(fast_tanh(v * ta), s1, s2);
            }
            __syncthreads();
            float iv = sGate[eb * G + ej];
            float gv = sGate[eb * G + 128 + ej];
            float ov = sGate[eb * G + 192 + ej];
            sHm[tid] = ov * fast_tanh(iv * gv);
            __syncthreads();
        }
        // ---- cell1 (weights from packed smem), src = sHm ----
        {
            ull acc[4];
            #pragma unroll
            for (int b = 0; b < 4; b++) acc[b] = 0ull;
            #pragma unroll
            for (int kg = 0; kg < 16; kg++) {
                ull w01 = sW1p[(2 * kg) * 256 + g];
                ull w23 = sW1p[(2 * kg + 1) * 256 + g];
                #pragma unroll
                for (int b = 0; b < 4; b++) {
                    ulonglong2 xv = *(const ulonglong2*)&sHm[b * 64 + kg * 4];
                    FMA2(acc[b], w01, xv.x);
                    FMA2(acc[b], w23, xv.y);
                }
            }
            float bias1 = sB1[g];
            #pragma unroll
            for (int b = 0; b < 4; b++) {
                float lo, hi;
                UNPACK2(lo, hi, acc[b]);
                float v = lo + hi + bias1;
                sGate[b * G + g] = fmaf(fast_tanh(v * ta), s1, s2);
            }
            __syncthreads();
            float iv = sGate[eb * G + ej];
            float gv = sGate[eb * G + 128 + ej];
            float ov = sGate[eb * G + 192 + ej];
            sHm[tid] = ov * fast_tanh(iv * gv);
            __syncthreads();
        }
        // ---- FC: one output per thread (eb, ej) ----
        {
            ull acc = 0ull;
            #pragma unroll
            for (int i = 0; i < 16; i++) {
                ull w01 = sWfcp[(2 * i) * 64 + ej];
                ull w23 = sWfcp[(2 * i + 1) * 64 + ej];
                ulonglong2 xv = *(const ulonglong2*)&sHm[eb * 64 + i * 4];
                FMA2(acc, w01, xv.x);
                FMA2(acc, w23, xv.y);
            }
            float lo, hi;
            UNPACK2(lo, hi, acc);
            float pred = lo + hi + sBfc[ej];
            out[(size_t)(b0 + eb) * PRED * HD + (size_t)s * HD + ej] = pred;
            sIn[tid] = pred;
            __syncthreads();
        }
    }
}

// ---------------------------------------------------------------------------
extern "C" void kernel_launch(void* const* d_in, const int* in_sizes, int n_in,
                              void* d_out, int out_size)
{
    const float* x    = (const float*)d_in[0];
    const float* Wih0 = (const float*)d_in[1];
    const float* Whh0 = (const float*)d_in[2];
    const float* bih0 = (const float*)d_in[3];
    const float* bhh0 = (const float*)d_in[4];
    const float* Wih1 = (const float*)d_in[5];
    const float* Whh1 = (const float*)d_in[6];
    const float* bih1 = (const float*)d_in[7];
    const float* bhh1 = (const float*)d_in[8];
    const float* Wfc  = (const float*)d_in[9];
    const float* bfc  = (const float*)d_in[10];
    float* out = (float*)d_out;

    float *pbuf = nullptr, *h1 = nullptr, *h2l = nullptr;
    cudaGetSymbolAddress((void**)&pbuf, g_p);
    cudaGetSymbolAddress((void**)&h1,   g_h1);
    cudaGetSymbolAddress((void**)&h2l,  g_h2last);

    const size_t smDec = (32 * 256 + 32 * 64) * sizeof(ull)
                       + (256 + 64 + 4 * 64 * 2 + 4 * G) * sizeof(float);
    cudaFuncSetAttribute(lstm_decoder, cudaFuncAttributeMaxDynamicSharedMemorySize, (int)smDec);

    input_gemm<<<296, 256>>>(x, Wih0, bih0, bhh0, pbuf, NROWS);
    lstm_recur<true ><<<256, 256>>>(pbuf, Whh0, h1);

    input_gemm<<<296, 256>>>(h1, Wih1, bih1, bhh1, pbuf, NROWS);
    lstm_recur<false><<<256, 256>>>(pbuf, Whh1, h2l);

    lstm_decoder<<<256, 256, smDec>>>(Wih0, bih0, bhh0, Wih1, bih1, bhh1,
                                      Wfc, bfc, h2l, out);
}